// round 2
// baseline (speedup 1.0000x reference)
#include <cuda_runtime.h>
#include <math.h>

#define BATCH   4
#define TLEN    512
#define EDIM    1024
#define VOCAB_N 32000
#define BEAM_N  64
#define RANK_N  32
#define MROWS   (BATCH * TLEN)   // 2048

// ---------------- scratch (static device globals; no runtime allocation) ----
__device__ int   g_beams[MROWS * BEAM_N];                       // 512 KB
__device__ float g_bemit[MROWS * BEAM_N];                       // 512 KB
__device__ float g_tm[BATCH * (TLEN - 1) * BEAM_N * BEAM_N];    // 33.5 MB

// ============================================================================
// 1) SGEMM: C[m,n] = sum_k A[m,k] * Bw[n,k] + bias[n]
//    A = modelout (2048 x 1024), Bw = W (32000 x 1024), both K-major (NT gemm)
//    128x128x16 tile, 256 threads, 8x8 register microtile.
// ============================================================================
__global__ void __launch_bounds__(256)
gemm_kernel(const float* __restrict__ A, const float* __restrict__ Bw,
            const float* __restrict__ bias, float* __restrict__ C)
{
    const int BM = 128, BN = 128, BK = 16;
    __shared__ float As[BK][BM];
    __shared__ float Bs[BK][BN];

    int tid  = threadIdx.x;
    int row0 = blockIdx.y * BM;
    int col0 = blockIdx.x * BN;
    int tx = tid & 15;        // 0..15 -> N microtiles
    int ty = tid >> 4;        // 0..15 -> M microtiles

    float acc[8][8];
#pragma unroll
    for (int i = 0; i < 8; i++)
#pragma unroll
        for (int j = 0; j < 8; j++) acc[i][j] = 0.f;

    for (int k0 = 0; k0 < EDIM; k0 += BK) {
        // load 128x16 of A and Bw, transposed into smem: 512 float4 each, 2/thread
#pragma unroll
        for (int i = 0; i < 2; i++) {
            int l  = tid + i * 256;
            int r  = l >> 2;     // row within tile (0..127)
            int c4 = l & 3;      // float4 within the 16-wide row
            float4 va = *(const float4*)(&A [(size_t)(row0 + r) * EDIM + k0 + c4 * 4]);
            As[c4 * 4 + 0][r] = va.x; As[c4 * 4 + 1][r] = va.y;
            As[c4 * 4 + 2][r] = va.z; As[c4 * 4 + 3][r] = va.w;
            float4 vb = *(const float4*)(&Bw[(size_t)(col0 + r) * EDIM + k0 + c4 * 4]);
            Bs[c4 * 4 + 0][r] = vb.x; Bs[c4 * 4 + 1][r] = vb.y;
            Bs[c4 * 4 + 2][r] = vb.z; Bs[c4 * 4 + 3][r] = vb.w;
        }
        __syncthreads();

#pragma unroll
        for (int k = 0; k < BK; k++) {
            float ra[8], rb[8];
            float4 a0 = *(const float4*)(&As[k][ty * 8]);
            float4 a1 = *(const float4*)(&As[k][ty * 8 + 4]);
            ra[0]=a0.x; ra[1]=a0.y; ra[2]=a0.z; ra[3]=a0.w;
            ra[4]=a1.x; ra[5]=a1.y; ra[6]=a1.z; ra[7]=a1.w;
            float4 b0 = *(const float4*)(&Bs[k][tx * 8]);
            float4 b1 = *(const float4*)(&Bs[k][tx * 8 + 4]);
            rb[0]=b0.x; rb[1]=b0.y; rb[2]=b0.z; rb[3]=b0.w;
            rb[4]=b1.x; rb[5]=b1.y; rb[6]=b1.z; rb[7]=b1.w;
#pragma unroll
            for (int i = 0; i < 8; i++)
#pragma unroll
                for (int j = 0; j < 8; j++)
                    acc[i][j] += ra[i] * rb[j];
        }
        __syncthreads();
    }

#pragma unroll
    for (int i = 0; i < 8; i++) {
        size_t rbase = (size_t)(row0 + ty * 8 + i) * VOCAB_N + col0 + tx * 8;
#pragma unroll
        for (int j = 0; j < 8; j++)
            C[rbase + j] = acc[i][j] + bias[col0 + tx * 8 + j];
    }
}

// ============================================================================
// 2) Exact top-64 per row via 4-pass radix select on order-preserving keys.
//    Target index forced to key=0xFFFFFFFF (matches "set to +inf" semantics).
//    Beam ORDER is irrelevant downstream (logsumexp is permutation-invariant).
// ============================================================================
__device__ __forceinline__ unsigned f2key(float x)
{
    unsigned u = __float_as_uint(x);
    return (u & 0x80000000u) ? ~u : (u | 0x80000000u);
}

__global__ void __launch_bounds__(256)
topk_kernel(const float* __restrict__ logits, const int* __restrict__ target)
{
    int row = blockIdx.x;
    const float* lrow = logits + (size_t)row * VOCAB_N;
    int tgt = target[row];
    int tid = threadIdx.x;

    __shared__ unsigned hist[256];
    __shared__ unsigned s_pref;
    __shared__ int s_want;
    __shared__ int cnt_gt, cnt_eq;

    if (tid == 0) { s_pref = 0u; s_want = BEAM_N; }
    __syncthreads();

    for (int pass = 0; pass < 4; pass++) {
        hist[tid] = 0;
        __syncthreads();
        unsigned pref = s_pref;
        int shift = 24 - pass * 8;
        for (int i = tid; i < VOCAB_N; i += 256) {
            unsigned key = (i == tgt) ? 0xFFFFFFFFu : f2key(lrow[i]);
            bool part = (pass == 0) || ((key >> (shift + 8)) == pref);
            if (part) atomicAdd(&hist[(key >> shift) & 0xFFu], 1u);
        }
        __syncthreads();
        if (tid == 0) {
            int want = s_want;
            unsigned cum = 0;
            for (int b = 255; b >= 0; b--) {
                unsigned c = hist[b];
                if (cum + c >= (unsigned)want) {
                    s_pref = (pref << 8) | (unsigned)b;
                    s_want = want - (int)cum;
                    break;
                }
                cum += c;
            }
        }
        __syncthreads();
    }

    unsigned thresh = s_pref;   // exact 64th-largest key
    int want = s_want;          // how many of the ==thresh keys to take
    int nGT  = BEAM_N - want;
    if (tid == 0) { cnt_gt = 0; cnt_eq = 0; }
    __syncthreads();

    for (int i = tid; i < VOCAB_N; i += 256) {
        unsigned key = (i == tgt) ? 0xFFFFFFFFu : f2key(lrow[i]);
        if (key > thresh) {
            int p = atomicAdd(&cnt_gt, 1);
            g_beams[row * BEAM_N + p] = i;
        } else if (key == thresh) {
            int p = atomicAdd(&cnt_eq, 1);
            if (p < want) g_beams[row * BEAM_N + nGT + p] = i;
        }
    }
    __syncthreads();

    if (tid < BEAM_N) {
        int idx = g_beams[row * BEAM_N + tid];
        g_bemit[row * BEAM_N + tid] = lrow[idx];  // original logit (not +inf)
    }
}

// ============================================================================
// 3) trans_mat[b,t,k,l] = dot(E1[beam[b,t,k]], E2[beam[b,t+1,l]])  (rank 32)
// ============================================================================
__global__ void __launch_bounds__(256)
transmat_kernel(const float* __restrict__ E1, const float* __restrict__ E2)
{
    int bt = blockIdx.x;           // 0 .. BATCH*(TLEN-1)-1
    int b  = bt / (TLEN - 1);
    int t  = bt % (TLEN - 1);
    int tid = threadIdx.x;

    __shared__ float s1[BEAM_N][RANK_N + 1];
    __shared__ float s2[BEAM_N][RANK_N + 1];

    const int* bm0 = g_beams + (size_t)(b * TLEN + t) * BEAM_N;
    const int* bm1 = bm0 + BEAM_N;

    for (int i = tid; i < BEAM_N * RANK_N; i += 256) {
        int k = i >> 5, r = i & 31;
        s1[k][r] = E1[(size_t)bm0[k] * RANK_N + r];
        s2[k][r] = E2[(size_t)bm1[k] * RANK_N + r];
    }
    __syncthreads();

    float* out = g_tm + (size_t)bt * (BEAM_N * BEAM_N);
    for (int o = tid; o < BEAM_N * BEAM_N; o += 256) {
        int kk = o >> 6, ll = o & 63;
        float acc = 0.f;
#pragma unroll
        for (int r = 0; r < RANK_N; r++) acc += s1[kk][r] * s2[ll][r];
        out[o] = acc;
    }
}

// ============================================================================
// 4) Forward recursion + numerator + final loss. One block per batch element.
// ============================================================================
__global__ void __launch_bounds__(64)
forward_kernel(const float* __restrict__ logits, const int* __restrict__ target,
               const float* __restrict__ E1, const float* __restrict__ E2,
               float* __restrict__ losses)
{
    int b = blockIdx.x;
    int l = threadIdx.x;
    __shared__ float sc[BEAM_N];
    __shared__ float red[BEAM_N];

    // ---- numerator: sum_t mask[t]*(emit[t] + (t>0 ? trans[t] : 0)) ----
    float np = 0.f;
    for (int t = l; t < TLEN; t += BEAM_N) {
        int tg = target[b * TLEN + t];
        if (tg != 0) {
            float e = logits[(size_t)(b * TLEN + t) * VOCAB_N + tg];
            float tr = 0.f;
            if (t > 0) {
                int tp = target[b * TLEN + t - 1];
#pragma unroll
                for (int r = 0; r < RANK_N; r++)
                    tr += E1[(size_t)tp * RANK_N + r] * E2[(size_t)tg * RANK_N + r];
            }
            np += e + tr;
        }
    }
    red[l] = np;
    sc[l]  = g_bemit[(size_t)(b * TLEN) * BEAM_N + l];   // score0 = beam_emit[:,0]
    __syncthreads();

    // ---- sequential scan over T ----
    for (int t = 1; t < TLEN; t++) {
        const float* tmrow = g_tm + (size_t)(b * (TLEN - 1) + t - 1) * (BEAM_N * BEAM_N);
        float v[BEAM_N];
        float mx = -3.4e38f;
#pragma unroll
        for (int k = 0; k < BEAM_N; k++) {
            v[k] = sc[k] + tmrow[k * BEAM_N + l];   // coalesced across l
            mx = fmaxf(mx, v[k]);
        }
        float s = 0.f;
#pragma unroll
        for (int k = 0; k < BEAM_N; k++) s += expf(v[k] - mx);
        float nxt = mx + logf(s) + g_bemit[(size_t)(b * TLEN + t) * BEAM_N + l];
        bool m = (target[b * TLEN + t] != 0);
        __syncthreads();
        if (m) sc[l] = nxt;
        __syncthreads();
    }

    if (l == 0) {
        float num = 0.f;
        for (int i = 0; i < BEAM_N; i++) num += red[i];
        float mx = sc[0];
        for (int i = 1; i < BEAM_N; i++) mx = fmaxf(mx, sc[i]);
        float s = 0.f;
        for (int i = 0; i < BEAM_N; i++) s += expf(sc[i] - mx);
        float den = mx + logf(s);
        losses[b] = -(num - den);
    }
}

// ============================================================================
extern "C" void kernel_launch(void* const* d_in, const int* in_sizes, int n_in,
                              void* d_out, int out_size)
{
    const float* modelout = (const float*)d_in[0];
    const float* W        = (const float*)d_in[1];
    const float* bias     = (const float*)d_in[2];
    const float* E1       = (const float*)d_in[3];
    const float* E2       = (const float*)d_in[4];
    const int*   target   = (const int*)  d_in[5];   // jnp.int64 -> int32 (JAX x64 off)

    float* logits = (float*)d_out;
    float* losses = logits + (size_t)MROWS * VOCAB_N;

    dim3 ggrid(VOCAB_N / 128, MROWS / 128);   // (250, 16)
    gemm_kernel<<<ggrid, 256>>>(modelout, W, bias, logits);
    topk_kernel<<<MROWS, 256>>>(logits, target);
    transmat_kernel<<<BATCH * (TLEN - 1), 256>>>(E1, E2);
    forward_kernel<<<BATCH, 64>>>(logits, target, E1, E2, losses);
}